// round 1
// baseline (speedup 1.0000x reference)
#include <cuda_runtime.h>
#include <cuda_bf16.h>

// Problem constants (from reference): N=100000, E=1600000, IN=128, H=OUT=64
#define NMAX 100000
#define HF   64

// Scratch (allocation-free: device globals)
__device__ float  g_hs [(size_t)NMAX * HF];   // h * dinv[row]  (gather source)
__device__ float  g_acc[(size_t)NMAX * HF];   // aggregation accumulator
__device__ float  g_dinv[NMAX];
__device__ int    g_deg [NMAX];
__device__ double g_sums[2 * HF];             // per-feature sum, sumsq
__device__ float  g_scale[HF];                // BN fused scale  (rsig*gamma)
__device__ float  g_shift[HF];                // BN fused shift  (beta - mu*rsig*gamma)

// ---------------------------------------------------------------------------
// Degree / norm
// ---------------------------------------------------------------------------
__global__ void deg_init_kernel(int n) {
    int i = blockIdx.x * blockDim.x + threadIdx.x;
    if (i < n) g_deg[i] = 1;  // self-loop
}

__global__ void deg_count_kernel(const int* __restrict__ dst, int E) {
    int i = blockIdx.x * blockDim.x + threadIdx.x;
    if (i < E) atomicAdd(&g_deg[dst[i]], 1);
}

__global__ void dinv_kernel(int n) {
    int i = blockIdx.x * blockDim.x + threadIdx.x;
    if (i < n) g_dinv[i] = rsqrtf((float)g_deg[i]);
}

__global__ void zero_sums_kernel() {
    if (threadIdx.x < 2 * HF) g_sums[threadIdx.x] = 0.0;
}

// ---------------------------------------------------------------------------
// GEMM: hs[row] = (transform(X[row]) @ W) * dinv[row]; acc[row] = hs[row]
// TRANS: input = acc (prev layer), apply  prelu((v*dinv)*scale + shift)
// Block tile: 128 rows x 64 cols, 256 threads, thread tile 8x4.
// ---------------------------------------------------------------------------
template<int K, bool TRANS>
__global__ void gemm_kernel(const float* __restrict__ Xin,
                            const float* __restrict__ W,
                            const float* __restrict__ alpha,
                            int n)
{
    constexpr int SXLD = 132;  // 132*4B stride: 16B-aligned rows, 4-way write conflicts only
    extern __shared__ float smem[];
    float* sW = smem;             // [K][64]
    float* sX = smem + K * 64;    // [K][SXLD]  (transposed tile)

    const float* X = TRANS ? g_acc : Xin;
    const int rowBase = blockIdx.x * 128;
    const int tid = threadIdx.x;

    for (int i = tid; i < K * 64; i += 256) sW[i] = W[i];

    for (int i = tid; i < 128 * K; i += 256) {
        int r = i / K, k = i - r * K;
        int row = rowBase + r;
        float v = 0.f;
        if (row < n) {
            v = X[row * K + k];
            if (TRANS) {
                v = v * g_dinv[row];
                v = v * g_scale[k] + g_shift[k];
                if (v < 0.f) v *= alpha[k];
            }
        }
        sX[k * SXLD + r] = v;
    }
    __syncthreads();

    const int tx = tid & 15;   // col group: cols tx*4 .. tx*4+3
    const int ty = tid >> 4;   // row group: rows ty*8 .. ty*8+7

    float a[8][4];
#pragma unroll
    for (int i = 0; i < 8; i++)
#pragma unroll
        for (int j = 0; j < 4; j++) a[i][j] = 0.f;

#pragma unroll 4
    for (int k = 0; k < K; k++) {
        float4 w  = *(const float4*)(sW + k * 64 + tx * 4);
        float4 xa = *(const float4*)(sX + k * SXLD + ty * 8);
        float4 xb = *(const float4*)(sX + k * SXLD + ty * 8 + 4);
        float xs[8] = {xa.x, xa.y, xa.z, xa.w, xb.x, xb.y, xb.z, xb.w};
#pragma unroll
        for (int i = 0; i < 8; i++) {
            a[i][0] += xs[i] * w.x;
            a[i][1] += xs[i] * w.y;
            a[i][2] += xs[i] * w.z;
            a[i][3] += xs[i] * w.w;
        }
    }

#pragma unroll
    for (int i = 0; i < 8; i++) {
        int row = rowBase + ty * 8 + i;
        if (row < n) {
            float dv = g_dinv[row];
            float4 h = make_float4(a[i][0] * dv, a[i][1] * dv, a[i][2] * dv, a[i][3] * dv);
            *(float4*)(g_hs  + (size_t)row * 64 + tx * 4) = h;
            *(float4*)(g_acc + (size_t)row * 64 + tx * 4) = h;  // self-loop init
        }
    }
}

// ---------------------------------------------------------------------------
// Edge scatter: acc[dst] += hs[src], 128-bit no-return reductions.
// One thread per float4 chunk (16 per edge).
// ---------------------------------------------------------------------------
__global__ void scatter_kernel(const int* __restrict__ src,
                               const int* __restrict__ dst, int E)
{
    int idx = blockIdx.x * blockDim.x + threadIdx.x;
    if (idx >= E * 16) return;
    int e = idx >> 4;
    int c = idx & 15;
    int s = __ldg(src + e);
    int d = __ldg(dst + e);
    float4 v = ((const float4*)g_hs)[(size_t)s * 16 + c];
    float4* p = ((float4*)g_acc) + (size_t)d * 16 + c;
    asm volatile("red.global.add.v4.f32 [%0], {%1, %2, %3, %4};"
                 :: "l"(p), "f"(v.x), "f"(v.y), "f"(v.z), "f"(v.w)
                 : "memory");
}

// ---------------------------------------------------------------------------
// BN stats over y = acc * dinv  (per-feature sum / sumsq, double accumulators)
// ---------------------------------------------------------------------------
__global__ void stats_kernel(int n)
{
    __shared__ float sh1[256], sh2[256];
    int t  = threadIdx.x;
    int f  = t & 63;
    int rg = t >> 6;
    int r0   = blockIdx.x * 256;
    int rend = min(n, r0 + 256);
    float s1 = 0.f, s2 = 0.f;
    for (int r = r0 + rg; r < rend; r += 4) {
        float v = g_acc[(size_t)r * 64 + f] * g_dinv[r];
        s1 += v;
        s2 += v * v;
    }
    sh1[t] = s1; sh2[t] = s2;
    __syncthreads();
    if (t < 64) {
        float a1 = sh1[t] + sh1[t + 64] + sh1[t + 128] + sh1[t + 192];
        float a2 = sh2[t] + sh2[t + 64] + sh2[t + 128] + sh2[t + 192];
        atomicAdd(&g_sums[t],      (double)a1);
        atomicAdd(&g_sums[64 + t], (double)a2);
    }
}

__global__ void finalize_kernel(const float* __restrict__ gam,
                                const float* __restrict__ bet,
                                double inv_n)
{
    int f = threadIdx.x;
    float mu  = (float)(g_sums[f] * inv_n);
    float var = (float)(g_sums[64 + f] * inv_n) - mu * mu;
    float rs  = rsqrtf(var + 1e-5f);
    float sc  = rs * gam[f];
    g_scale[f] = sc;
    g_shift[f] = bet[f] - mu * sc;
}

// ---------------------------------------------------------------------------
// Final output: d_out = prelu((acc*dinv)*scale + shift, alpha3)
// ---------------------------------------------------------------------------
__global__ void out_kernel(const float* __restrict__ alpha,
                           float* __restrict__ out, int n)
{
    int idx = blockIdx.x * blockDim.x + threadIdx.x;
    if (idx >= n * 64) return;
    int r = idx >> 6;
    int f = idx & 63;
    float v = g_acc[idx] * g_dinv[r] * g_scale[f] + g_shift[f];
    out[idx] = (v >= 0.f) ? v : alpha[f] * v;
}

// ---------------------------------------------------------------------------
// Launch
// ---------------------------------------------------------------------------
extern "C" void kernel_launch(void* const* d_in, const int* in_sizes, int n_in,
                              void* d_out, int out_size)
{
    const float* x   = (const float*)d_in[0];
    const int*   ei  = (const int*)  d_in[1];
    const int N = in_sizes[0] / 128;
    const int E = in_sizes[1] / 2;
    const int* src = ei;
    const int* dst = ei + E;

    const float* W1  = (const float*)d_in[2];
    const float* G1  = (const float*)d_in[4];
    const float* BE1 = (const float*)d_in[5];
    const float* A1  = (const float*)d_in[6];
    const float* W2  = (const float*)d_in[7];
    const float* G2  = (const float*)d_in[9];
    const float* BE2 = (const float*)d_in[10];
    const float* A2  = (const float*)d_in[11];
    const float* W3  = (const float*)d_in[12];
    const float* G3  = (const float*)d_in[14];
    const float* BE3 = (const float*)d_in[15];
    const float* A3  = (const float*)d_in[16];

    const int smem128 = (128 * 64 + 128 * 132) * 4;  // ~100 KB
    const int smem64  = (64 * 64  + 64 * 132)  * 4;  // ~50 KB
    cudaFuncSetAttribute((const void*)gemm_kernel<128, false>,
                         cudaFuncAttributeMaxDynamicSharedMemorySize, smem128);
    cudaFuncSetAttribute((const void*)gemm_kernel<64, true>,
                         cudaFuncAttributeMaxDynamicSharedMemorySize, smem64);

    const int gN = (N + 255) / 256;
    const int gE = (E + 255) / 256;
    const int gG = (N + 127) / 128;
    const int gS = (E * 16 + 255) / 256;
    const int gO = (N * 64 + 255) / 256;
    const double inv_n = 1.0 / (double)N;

    deg_init_kernel <<<gN, 256>>>(N);
    deg_count_kernel<<<gE, 256>>>(dst, E);
    dinv_kernel     <<<gN, 256>>>(N);

    // ---- Layer 1 ----
    zero_sums_kernel<<<1, 128>>>();
    gemm_kernel<128, false><<<gG, 256, smem128>>>(x, W1, nullptr, N);
    scatter_kernel  <<<gS, 256>>>(src, dst, E);
    stats_kernel    <<<gN, 256>>>(N);
    finalize_kernel <<<1, 64>>>(G1, BE1, inv_n);

    // ---- Layer 2 ----
    zero_sums_kernel<<<1, 128>>>();
    gemm_kernel<64, true><<<gG, 256, smem64>>>(nullptr, W2, A1, N);
    scatter_kernel  <<<gS, 256>>>(src, dst, E);
    stats_kernel    <<<gN, 256>>>(N);
    finalize_kernel <<<1, 64>>>(G2, BE2, inv_n);

    // ---- Layer 3 ----
    zero_sums_kernel<<<1, 128>>>();
    gemm_kernel<64, true><<<gG, 256, smem64>>>(nullptr, W3, A2, N);
    scatter_kernel  <<<gS, 256>>>(src, dst, E);
    stats_kernel    <<<gN, 256>>>(N);
    finalize_kernel <<<1, 64>>>(G3, BE3, inv_n);

    out_kernel<<<gO, 256>>>(A3, (float*)d_out, N);
}

// round 2
// speedup vs baseline: 1.3426x; 1.3426x over previous
#include <cuda_runtime.h>
#include <cuda_bf16.h>

// Problem constants: N=100000, E=1600000, IN=128, H=OUT=64
#define NMAX 100000
#define EMAX 1600000
#define HF   64

// Scratch (allocation-free device globals)
__device__ float  g_hs [(size_t)NMAX * HF];   // (X@W) * dinv[row]  (message values)
__device__ float  g_acc[(size_t)NMAX * HF];   // post-aggregation, post-dinv (= GCN out pre-BN)
__device__ float  g_dinv[NMAX];
__device__ int    g_deg [NMAX];               // edge-only in-degree
__device__ int    g_off [NMAX + 1];           // CSR row offsets (by dst)
__device__ int    g_cursor[NMAX];
__device__ int    g_adj [EMAX];               // src ids grouped by dst
__device__ int    g_bsum[256];                // block sums for scan
__device__ int    g_bpre[256];
__device__ double g_sums[2 * HF];             // per-feature sum, sumsq
__device__ float  g_scale[HF];
__device__ float  g_shift[HF];

// ---------------------------------------------------------------------------
// Degree / CSR build (counting sort by dst)
// ---------------------------------------------------------------------------
__global__ void deg_init_kernel(int n) {
    int i = blockIdx.x * blockDim.x + threadIdx.x;
    if (i < n) g_deg[i] = 0;
}

__global__ void deg_count_kernel(const int* __restrict__ dst, int E) {
    int i = blockIdx.x * blockDim.x + threadIdx.x;
    if (i < E) atomicAdd(&g_deg[dst[i]], 1);
}

__global__ void dinv_kernel(int n) {
    int i = blockIdx.x * blockDim.x + threadIdx.x;
    if (i < n) g_dinv[i] = rsqrtf((float)(g_deg[i] + 1));  // +1 self-loop
}

// per-1024-node block sums
__global__ void scan_bsum_kernel(int n) {
    __shared__ int sh[256];
    int b = blockIdx.x, t = threadIdx.x;
    int base = b * 1024;
    int s = 0;
    for (int i = t; i < 1024; i += 256) {
        int idx = base + i;
        if (idx < n) s += g_deg[idx];
    }
    sh[t] = s;
    __syncthreads();
    for (int o = 128; o > 0; o >>= 1) {
        if (t < o) sh[t] += sh[t + o];
        __syncthreads();
    }
    if (t == 0) g_bsum[b] = sh[0];
}

// sequential scan of block sums (tiny: ~98 entries)
__global__ void scan_tops_kernel(int nb, int n, int E) {
    if (threadIdx.x == 0) {
        int run = 0;
        for (int i = 0; i < nb; i++) { g_bpre[i] = run; run += g_bsum[i]; }
        g_off[n] = E;
    }
}

// in-block exclusive scan + add block prefix
__global__ void scan_final_kernel(int n) {
    __shared__ int sh[1024];
    int b = blockIdx.x, t = threadIdx.x;
    int idx = b * 1024 + t;
    int v = (idx < n) ? g_deg[idx] : 0;
    sh[t] = v;
    for (int o = 1; o < 1024; o <<= 1) {
        __syncthreads();
        int u = (t >= o) ? sh[t - o] : 0;
        __syncthreads();
        sh[t] += u;
    }
    __syncthreads();
    if (idx < n) {
        int ex = sh[t] - v + g_bpre[b];
        g_off[idx]    = ex;
        g_cursor[idx] = ex;
    }
}

__global__ void fill_adj_kernel(const int* __restrict__ src,
                                const int* __restrict__ dst, int E) {
    int i = blockIdx.x * blockDim.x + threadIdx.x;
    if (i < E) {
        int pos = atomicAdd(&g_cursor[dst[i]], 1);
        g_adj[pos] = src[i];
    }
}

__global__ void zero_sums_kernel() {
    if (threadIdx.x < 2 * HF) g_sums[threadIdx.x] = 0.0;
}

// ---------------------------------------------------------------------------
// GEMM: hs[row] = (transform(in[row]) @ W) * dinv[row]
// TRANS: in = g_acc (already post-dinv), apply  prelu(v*scale + shift)
// Block tile 128x64, 256 threads, thread tile 8x4.
// ---------------------------------------------------------------------------
template<int K, bool TRANS>
__global__ void gemm_kernel(const float* __restrict__ Xin,
                            const float* __restrict__ W,
                            const float* __restrict__ alpha,
                            int n)
{
    constexpr int SXLD = 132;
    extern __shared__ float smem[];
    float* sW = smem;             // [K][64]
    float* sX = smem + K * 64;    // [K][SXLD] transposed

    const float* X = TRANS ? g_acc : Xin;
    const int rowBase = blockIdx.x * 128;
    const int tid = threadIdx.x;

    for (int i = tid; i < K * 64; i += 256) sW[i] = W[i];

    for (int i = tid; i < 128 * K; i += 256) {
        int r = i / K, k = i - r * K;
        int row = rowBase + r;
        float v = 0.f;
        if (row < n) {
            v = X[row * K + k];
            if (TRANS) {
                v = v * g_scale[k] + g_shift[k];
                if (v < 0.f) v *= alpha[k];
            }
        }
        sX[k * SXLD + r] = v;
    }
    __syncthreads();

    const int tx = tid & 15;
    const int ty = tid >> 4;

    float a[8][4];
#pragma unroll
    for (int i = 0; i < 8; i++)
#pragma unroll
        for (int j = 0; j < 4; j++) a[i][j] = 0.f;

#pragma unroll 4
    for (int k = 0; k < K; k++) {
        float4 w  = *(const float4*)(sW + k * 64 + tx * 4);
        float4 xa = *(const float4*)(sX + k * SXLD + ty * 8);
        float4 xb = *(const float4*)(sX + k * SXLD + ty * 8 + 4);
        float xs[8] = {xa.x, xa.y, xa.z, xa.w, xb.x, xb.y, xb.z, xb.w};
#pragma unroll
        for (int i = 0; i < 8; i++) {
            a[i][0] += xs[i] * w.x;
            a[i][1] += xs[i] * w.y;
            a[i][2] += xs[i] * w.z;
            a[i][3] += xs[i] * w.w;
        }
    }

#pragma unroll
    for (int i = 0; i < 8; i++) {
        int row = rowBase + ty * 8 + i;
        if (row < n) {
            float dv = g_dinv[row];
            float4 h = make_float4(a[i][0] * dv, a[i][1] * dv, a[i][2] * dv, a[i][3] * dv);
            *(float4*)(g_hs + (size_t)row * 64 + tx * 4) = h;
        }
    }
}

// ---------------------------------------------------------------------------
// CSR gather: acc[v] = dinv[v] * (hs[v] + sum_{e in adj(v)} hs[adj[e]])
// 16 threads (float4 chunks) per node.
// ---------------------------------------------------------------------------
__global__ void gather_kernel(int n)
{
    int idx = blockIdx.x * blockDim.x + threadIdx.x;
    int v = idx >> 4;
    int c = idx & 15;
    if (v >= n) return;
    int e0 = g_off[v];
    int e1 = g_off[v + 1];
    float4 tot = ((const float4*)g_hs)[(size_t)v * 16 + c];  // self-loop
    for (int e = e0; e < e1; e++) {
        int s = __ldg(&g_adj[e]);
        float4 m = ((const float4*)g_hs)[(size_t)s * 16 + c];
        tot.x += m.x; tot.y += m.y; tot.z += m.z; tot.w += m.w;
    }
    float dv = g_dinv[v];
    tot.x *= dv; tot.y *= dv; tot.z *= dv; tot.w *= dv;
    ((float4*)g_acc)[(size_t)v * 16 + c] = tot;
}

// ---------------------------------------------------------------------------
// BN stats over g_acc (already the pre-BN activations)
// ---------------------------------------------------------------------------
__global__ void stats_kernel(int n)
{
    __shared__ float sh1[256], sh2[256];
    int t  = threadIdx.x;
    int f  = t & 63;
    int rg = t >> 6;
    int r0   = blockIdx.x * 256;
    int rend = min(n, r0 + 256);
    float s1 = 0.f, s2 = 0.f;
    for (int r = r0 + rg; r < rend; r += 4) {
        float v = g_acc[(size_t)r * 64 + f];
        s1 += v;
        s2 += v * v;
    }
    sh1[t] = s1; sh2[t] = s2;
    __syncthreads();
    if (t < 64) {
        float a1 = sh1[t] + sh1[t + 64] + sh1[t + 128] + sh1[t + 192];
        float a2 = sh2[t] + sh2[t + 64] + sh2[t + 128] + sh2[t + 192];
        atomicAdd(&g_sums[t],      (double)a1);
        atomicAdd(&g_sums[64 + t], (double)a2);
    }
}

__global__ void finalize_kernel(const float* __restrict__ gam,
                                const float* __restrict__ bet,
                                double inv_n)
{
    int f = threadIdx.x;
    float mu  = (float)(g_sums[f] * inv_n);
    float var = (float)(g_sums[64 + f] * inv_n) - mu * mu;
    float rs  = rsqrtf(var + 1e-5f);
    float sc  = rs * gam[f];
    g_scale[f] = sc;
    g_shift[f] = bet[f] - mu * sc;
}

__global__ void out_kernel(const float* __restrict__ alpha,
                           float* __restrict__ out, int n)
{
    int idx = blockIdx.x * blockDim.x + threadIdx.x;
    if (idx >= n * 64) return;
    int f = idx & 63;
    float v = g_acc[idx] * g_scale[f] + g_shift[f];
    out[idx] = (v >= 0.f) ? v : alpha[f] * v;
}

// ---------------------------------------------------------------------------
// Launch
// ---------------------------------------------------------------------------
extern "C" void kernel_launch(void* const* d_in, const int* in_sizes, int n_in,
                              void* d_out, int out_size)
{
    const float* x   = (const float*)d_in[0];
    const int*   ei  = (const int*)  d_in[1];
    const int N = in_sizes[0] / 128;
    const int E = in_sizes[1] / 2;
    const int* src = ei;
    const int* dst = ei + E;

    const float* W1  = (const float*)d_in[2];
    const float* G1  = (const float*)d_in[4];
    const float* BE1 = (const float*)d_in[5];
    const float* A1  = (const float*)d_in[6];
    const float* W2  = (const float*)d_in[7];
    const float* G2  = (const float*)d_in[9];
    const float* BE2 = (const float*)d_in[10];
    const float* A2  = (const float*)d_in[11];
    const float* W3  = (const float*)d_in[12];
    const float* G3  = (const float*)d_in[14];
    const float* BE3 = (const float*)d_in[15];
    const float* A3  = (const float*)d_in[16];

    const int smem128 = (128 * 64 + 128 * 132) * 4;
    const int smem64  = (64 * 64  + 64 * 132)  * 4;
    cudaFuncSetAttribute((const void*)gemm_kernel<128, false>,
                         cudaFuncAttributeMaxDynamicSharedMemorySize, smem128);
    cudaFuncSetAttribute((const void*)gemm_kernel<64, true>,
                         cudaFuncAttributeMaxDynamicSharedMemorySize, smem64);

    const int gN  = (N + 255) / 256;
    const int gE  = (E + 255) / 256;
    const int gG  = (N + 127) / 128;
    const int gGa = (N * 16 + 255) / 256;
    const int gO  = (N * 64 + 255) / 256;
    const int nb  = (N + 1023) / 1024;
    const double inv_n = 1.0 / (double)N;

    // CSR build (once per launch, reused by all 3 layers)
    deg_init_kernel  <<<gN, 256>>>(N);
    deg_count_kernel <<<gE, 256>>>(dst, E);
    dinv_kernel      <<<gN, 256>>>(N);
    scan_bsum_kernel <<<nb, 256>>>(N);
    scan_tops_kernel <<<1, 32>>>(nb, N, E);
    scan_final_kernel<<<nb, 1024>>>(N);
    fill_adj_kernel  <<<gE, 256>>>(src, dst, E);

    // ---- Layer 1 ----
    zero_sums_kernel<<<1, 128>>>();
    gemm_kernel<128, false><<<gG, 256, smem128>>>(x, W1, nullptr, N);
    gather_kernel   <<<gGa, 256>>>(N);
    stats_kernel    <<<gN, 256>>>(N);
    finalize_kernel <<<1, 64>>>(G1, BE1, inv_n);

    // ---- Layer 2 ----
    zero_sums_kernel<<<1, 128>>>();
    gemm_kernel<64, true><<<gG, 256, smem64>>>(nullptr, W2, A1, N);
    gather_kernel   <<<gGa, 256>>>(N);
    stats_kernel    <<<gN, 256>>>(N);
    finalize_kernel <<<1, 64>>>(G2, BE2, inv_n);

    // ---- Layer 3 ----
    zero_sums_kernel<<<1, 128>>>();
    gemm_kernel<64, true><<<gG, 256, smem64>>>(nullptr, W3, A2, N);
    gather_kernel   <<<gGa, 256>>>(N);
    stats_kernel    <<<gN, 256>>>(N);
    finalize_kernel <<<1, 64>>>(G3, BE3, inv_n);

    out_kernel<<<gO, 256>>>(A3, (float*)d_out, N);
}

// round 4
// speedup vs baseline: 1.5082x; 1.1234x over previous
#include <cuda_runtime.h>
#include <cuda_bf16.h>
#include <stdint.h>

// Problem constants: N=100000, E=1600000, IN=128, H=OUT=64
#define NMAX 100000
#define EMAX 1600000
#define HF   64

// Scratch (allocation-free device globals)
__device__ float  g_hs [(size_t)NMAX * HF];
__device__ float  g_acc[(size_t)NMAX * HF];
__device__ float  g_dinv[NMAX];
__device__ int    g_deg [NMAX];
__device__ int    g_off [NMAX + 1];
__device__ int    g_cursor[NMAX];
__device__ int    g_adj [EMAX];
__device__ int    g_bsum[256];
__device__ int    g_bpre[256];
__device__ double g_sums[2 * HF];
__device__ float  g_scale[HF];
__device__ float  g_shift[HF];

// ---------------------------------------------------------------------------
// MMA helpers (HMMA bf16 — plain sm_80+ PTX, no 'a' target features)
// ---------------------------------------------------------------------------
__device__ __forceinline__ uint32_t smem_u32(const void* p) {
    uint32_t a;
    asm("{ .reg .u64 t; cvta.to.shared.u64 t, %1; cvt.u32.u64 %0, t; }"
        : "=r"(a) : "l"(p));
    return a;
}

__device__ __forceinline__ void ldsm_x4(uint32_t* r, uint32_t addr) {
    asm volatile("ldmatrix.sync.aligned.m8n8.x4.shared.b16 {%0,%1,%2,%3}, [%4];"
                 : "=r"(r[0]), "=r"(r[1]), "=r"(r[2]), "=r"(r[3]) : "r"(addr));
}

__device__ __forceinline__ void ldsm_x2(uint32_t* r, uint32_t addr) {
    asm volatile("ldmatrix.sync.aligned.m8n8.x2.shared.b16 {%0,%1}, [%2];"
                 : "=r"(r[0]), "=r"(r[1]) : "r"(addr));
}

__device__ __forceinline__ void mma_bf16(float* c, const uint32_t* a, const uint32_t* b) {
    asm volatile("mma.sync.aligned.m16n8k16.row.col.f32.bf16.bf16.f32 "
                 "{%0,%1,%2,%3}, {%4,%5,%6,%7}, {%8,%9}, {%0,%1,%2,%3};"
                 : "+f"(c[0]), "+f"(c[1]), "+f"(c[2]), "+f"(c[3])
                 : "r"(a[0]), "r"(a[1]), "r"(a[2]), "r"(a[3]),
                   "r"(b[0]), "r"(b[1]));
}

__device__ __forceinline__ uint32_t pack_bf2(__nv_bfloat16 lo, __nv_bfloat16 hi) {
    __nv_bfloat162 t(lo, hi);
    return *(uint32_t*)&t;
}

__device__ __forceinline__ uint2 split4(float4 v) {
    // returns {hi pair01, hi pair23} — caller gets lo via second call
    __nv_bfloat16 h0 = __float2bfloat16(v.x), h1 = __float2bfloat16(v.y);
    __nv_bfloat16 h2 = __float2bfloat16(v.z), h3 = __float2bfloat16(v.w);
    return make_uint2(pack_bf2(h0, h1), pack_bf2(h2, h3));
}

// ---------------------------------------------------------------------------
// Degree / CSR build
// ---------------------------------------------------------------------------
__global__ void deg_init_kernel(int n) {
    int i = blockIdx.x * blockDim.x + threadIdx.x;
    if (i < n) g_deg[i] = 0;
    if (blockIdx.x == 0 && threadIdx.x < 2 * HF) g_sums[threadIdx.x] = 0.0;
}

__global__ void deg_count_kernel(const int* __restrict__ dst, int E) {
    int i = blockIdx.x * blockDim.x + threadIdx.x;
    if (i < E) atomicAdd(&g_deg[dst[i]], 1);
}

__global__ void scan_bsum_kernel(int n) {
    __shared__ int sh[256];
    int b = blockIdx.x, t = threadIdx.x;
    int base = b * 1024;
    int s = 0;
    for (int i = t; i < 1024; i += 256) {
        int idx = base + i;
        if (idx < n) s += g_deg[idx];
    }
    sh[t] = s;
    __syncthreads();
    for (int o = 128; o > 0; o >>= 1) {
        if (t < o) sh[t] += sh[t + o];
        __syncthreads();
    }
    if (t == 0) g_bsum[b] = sh[0];
}

__global__ void scan_tops_kernel(int nb, int n, int E) {
    if (threadIdx.x == 0) {
        int run = 0;
        for (int i = 0; i < nb; i++) { g_bpre[i] = run; run += g_bsum[i]; }
        g_off[n] = E;
    }
}

__global__ void scan_final_kernel(int n) {
    __shared__ int sh[1024];
    int b = blockIdx.x, t = threadIdx.x;
    int idx = b * 1024 + t;
    int v = (idx < n) ? g_deg[idx] : 0;
    sh[t] = v;
    for (int o = 1; o < 1024; o <<= 1) {
        __syncthreads();
        int u = (t >= o) ? sh[t - o] : 0;
        __syncthreads();
        sh[t] += u;
    }
    __syncthreads();
    if (idx < n) {
        int ex = sh[t] - v + g_bpre[b];
        g_off[idx]    = ex;
        g_cursor[idx] = ex;
        g_dinv[idx]   = rsqrtf((float)(v + 1));
    }
}

__global__ void fill_adj_kernel(const int* __restrict__ src,
                                const int* __restrict__ dst, int E) {
    int i = blockIdx.x * blockDim.x + threadIdx.x;
    if (i < E) {
        int pos = atomicAdd(&g_cursor[dst[i]], 1);
        g_adj[pos] = src[i];
    }
}

// ---------------------------------------------------------------------------
// HMMA GEMM: hs[row] = (transform(in[row]) @ W) * dinv[row]
// Split-bf16 3-pass: hi*hi + hi*lo + lo*hi, fp32 register accumulation.
// CTA tile 128x64, 8 warps (4x2 grid of 32x32 warp tiles), 256 threads.
// SMEM: padded row-major bf16, LDA = K+8 halves (ldmatrix conflict-free).
// ---------------------------------------------------------------------------
template<int K, bool TRANS>
__global__ void __launch_bounds__(256, 1)
gemm_mma_kernel(const float* __restrict__ Xin,
                const float* __restrict__ W,
                const float* __restrict__ alpha,
                int n)
{
    constexpr int LDA  = K + 8;                 // halves
    constexpr int A_HI = 0;                     // [128][LDA]
    constexpr int A_LO = 128 * LDA;
    constexpr int B_HI = 256 * LDA;             // [64][LDA]  (W^T, rows n, cols k)
    constexpr int B_LO = 256 * LDA + 64 * LDA;

    extern __shared__ __nv_bfloat16 smem[];
    const uint32_t sb = smem_u32(smem);
    const int tid = threadIdx.x;
    const int wid = tid >> 5, lid = tid & 31;
    const int rowBase = blockIdx.x * 128;

    // ---- A tile: load f32, split to bf16 hi/lo ----
    const float* X = TRANS ? g_acc : Xin;
    for (int i = tid; i < 128 * (K / 4); i += 256) {
        int r  = i / (K / 4);
        int k0 = (i % (K / 4)) * 4;
        float4 v = make_float4(0.f, 0.f, 0.f, 0.f);
        int row = rowBase + r;
        if (row < n) {
            v = *(const float4*)(X + (size_t)row * K + k0);
            if (TRANS) {
                float t;
                t = v.x * g_scale[k0+0] + g_shift[k0+0]; v.x = (t >= 0.f) ? t : t * alpha[k0+0];
                t = v.y * g_scale[k0+1] + g_shift[k0+1]; v.y = (t >= 0.f) ? t : t * alpha[k0+1];
                t = v.z * g_scale[k0+2] + g_shift[k0+2]; v.z = (t >= 0.f) ? t : t * alpha[k0+2];
                t = v.w * g_scale[k0+3] + g_shift[k0+3]; v.w = (t >= 0.f) ? t : t * alpha[k0+3];
            }
        }
        uint2 hi = split4(v);
        float4 res = make_float4(
            v.x - __bfloat162float(__float2bfloat16(v.x)),
            v.y - __bfloat162float(__float2bfloat16(v.y)),
            v.z - __bfloat162float(__float2bfloat16(v.z)),
            v.w - __bfloat162float(__float2bfloat16(v.w)));
        uint2 lo = split4(res);
        *(uint2*)(smem + A_HI + r * LDA + k0) = hi;
        *(uint2*)(smem + A_LO + r * LDA + k0) = lo;
    }

    // ---- B tile: W^T [64 x K] ----
    for (int i = tid; i < 64 * (K / 4); i += 256) {
        int nn = i / (K / 4);
        int k0 = (i % (K / 4)) * 4;
        float4 v = make_float4(W[(size_t)(k0+0) * 64 + nn], W[(size_t)(k0+1) * 64 + nn],
                               W[(size_t)(k0+2) * 64 + nn], W[(size_t)(k0+3) * 64 + nn]);
        uint2 hi = split4(v);
        float4 res = make_float4(
            v.x - __bfloat162float(__float2bfloat16(v.x)),
            v.y - __bfloat162float(__float2bfloat16(v.y)),
            v.z - __bfloat162float(__float2bfloat16(v.z)),
            v.w - __bfloat162float(__float2bfloat16(v.w)));
        uint2 lo = split4(res);
        *(uint2*)(smem + B_HI + nn * LDA + k0) = hi;
        *(uint2*)(smem + B_LO + nn * LDA + k0) = lo;
    }
    __syncthreads();

    // ---- Compute: warp (4 rows x 2 cols), warp tile 32x32 ----
    const int warpRow = wid & 3;
    const int warpCol = wid >> 2;

    float acc[2][4][4];
#pragma unroll
    for (int mi = 0; mi < 2; mi++)
#pragma unroll
        for (int ni = 0; ni < 4; ni++)
#pragma unroll
            for (int j = 0; j < 4; j++) acc[mi][ni][j] = 0.f;

    // ldmatrix lane address offsets (in halves)
    const int aRow  = warpRow * 32 + (lid & 15);   // + mi*16
    const int aKoff = (lid >> 4) * 8;
    const int bRow  = warpCol * 32 + (lid & 7);    // + ni*8
    const int bKoff = ((lid >> 3) & 1) * 8;

#pragma unroll
    for (int k0 = 0; k0 < K; k0 += 16) {
        uint32_t aHi[2][4], aLo[2][4], bHi[4][2], bLo[4][2];
#pragma unroll
        for (int mi = 0; mi < 2; mi++) {
            uint32_t base = (uint32_t)(((aRow + mi * 16) * LDA + k0 + aKoff) * 2);
            ldsm_x4(aHi[mi], sb + A_HI * 2 + base);
            ldsm_x4(aLo[mi], sb + A_LO * 2 + base);
        }
#pragma unroll
        for (int ni = 0; ni < 4; ni++) {
            uint32_t base = (uint32_t)(((bRow + ni * 8) * LDA + k0 + bKoff) * 2);
            ldsm_x2(bHi[ni], sb + B_HI * 2 + base);
            ldsm_x2(bLo[ni], sb + B_LO * 2 + base);
        }
#pragma unroll
        for (int mi = 0; mi < 2; mi++)
#pragma unroll
            for (int ni = 0; ni < 4; ni++) {
                mma_bf16(acc[mi][ni], aHi[mi], bHi[ni]);
                mma_bf16(acc[mi][ni], aHi[mi], bLo[ni]);
                mma_bf16(acc[mi][ni], aLo[mi], bHi[ni]);
            }
    }

    // ---- Epilogue: scale by dinv, store ----
    const int rBase = rowBase + warpRow * 32 + (lid >> 2);
    const int cBase = warpCol * 32 + (lid & 3) * 2;
#pragma unroll
    for (int mi = 0; mi < 2; mi++) {
#pragma unroll
        for (int h = 0; h < 2; h++) {
            int row = rBase + mi * 16 + h * 8;
            if (row < n) {
                float dv = g_dinv[row];
                float* o = g_hs + (size_t)row * 64;
#pragma unroll
                for (int ni = 0; ni < 4; ni++) {
                    float2 v = make_float2(acc[mi][ni][h * 2 + 0] * dv,
                                           acc[mi][ni][h * 2 + 1] * dv);
                    *(float2*)(o + cBase + ni * 8) = v;
                }
            }
        }
    }
}

// ---------------------------------------------------------------------------
// CSR gather: acc[v] = dinv[v] * (hs[v] + sum_{adj} hs[s])
// ---------------------------------------------------------------------------
__global__ void gather_kernel(int n)
{
    int idx = blockIdx.x * blockDim.x + threadIdx.x;
    int v = idx >> 4;
    int c = idx & 15;
    if (v >= n) return;
    int e0 = g_off[v];
    int e1 = g_off[v + 1];
    float4 tot = ((const float4*)g_hs)[(size_t)v * 16 + c];
    for (int e = e0; e < e1; e++) {
        int s = __ldg(&g_adj[e]);
        float4 m = ((const float4*)g_hs)[(size_t)s * 16 + c];
        tot.x += m.x; tot.y += m.y; tot.z += m.z; tot.w += m.w;
    }
    float dv = g_dinv[v];
    tot.x *= dv; tot.y *= dv; tot.z *= dv; tot.w *= dv;
    ((float4*)g_acc)[(size_t)v * 16 + c] = tot;
}

// ---------------------------------------------------------------------------
// BN stats / finalize / output
// ---------------------------------------------------------------------------
__global__ void stats_kernel(int n)
{
    __shared__ float sh1[256], sh2[256];
    int t  = threadIdx.x;
    int f  = t & 63;
    int rg = t >> 6;
    int r0   = blockIdx.x * 256;
    int rend = min(n, r0 + 256);
    float s1 = 0.f, s2 = 0.f;
    for (int r = r0 + rg; r < rend; r += 4) {
        float v = g_acc[(size_t)r * 64 + f];
        s1 += v;
        s2 += v * v;
    }
    sh1[t] = s1; sh2[t] = s2;
    __syncthreads();
    if (t < 64) {
        float a1 = sh1[t] + sh1[t + 64] + sh1[t + 128] + sh1[t + 192];
        float a2 = sh2[t] + sh2[t + 64] + sh2[t + 128] + sh2[t + 192];
        atomicAdd(&g_sums[t],      (double)a1);
        atomicAdd(&g_sums[64 + t], (double)a2);
    }
}

__global__ void finalize_kernel(const float* __restrict__ gam,
                                const float* __restrict__ bet,
                                double inv_n)
{
    int f = threadIdx.x;
    float mu  = (float)(g_sums[f] * inv_n);
    float var = (float)(g_sums[64 + f] * inv_n) - mu * mu;
    float rs  = rsqrtf(var + 1e-5f);
    float sc  = rs * gam[f];
    g_scale[f] = sc;
    g_shift[f] = bet[f] - mu * sc;
    g_sums[f] = 0.0;
    g_sums[64 + f] = 0.0;
}

__global__ void out_kernel(const float* __restrict__ alpha,
                           float* __restrict__ out, int n)
{
    int idx = blockIdx.x * blockDim.x + threadIdx.x;
    if (idx >= n * 64) return;
    int f = idx & 63;
    float v = g_acc[idx] * g_scale[f] + g_shift[f];
    out[idx] = (v >= 0.f) ? v : alpha[f] * v;
}

// ---------------------------------------------------------------------------
// Launch
// ---------------------------------------------------------------------------
extern "C" void kernel_launch(void* const* d_in, const int* in_sizes, int n_in,
                              void* d_out, int out_size)
{
    const float* x   = (const float*)d_in[0];
    const int*   ei  = (const int*)  d_in[1];
    const int N = in_sizes[0] / 128;
    const int E = in_sizes[1] / 2;
    const int* src = ei;
    const int* dst = ei + E;

    const float* W1  = (const float*)d_in[2];
    const float* G1  = (const float*)d_in[4];
    const float* BE1 = (const float*)d_in[5];
    const float* A1  = (const float*)d_in[6];
    const float* W2  = (const float*)d_in[7];
    const float* G2  = (const float*)d_in[9];
    const float* BE2 = (const float*)d_in[10];
    const float* A2  = (const float*)d_in[11];
    const float* W3  = (const float*)d_in[12];
    const float* G3  = (const float*)d_in[14];
    const float* BE3 = (const float*)d_in[15];
    const float* A3  = (const float*)d_in[16];

    const int smem128 = 384 * (128 + 8) * 2;  // 104448 B
    const int smem64  = 384 * (64 + 8) * 2;   //  55296 B
    cudaFuncSetAttribute((const void*)gemm_mma_kernel<128, false>,
                         cudaFuncAttributeMaxDynamicSharedMemorySize, smem128);
    cudaFuncSetAttribute((const void*)gemm_mma_kernel<64, true>,
                         cudaFuncAttributeMaxDynamicSharedMemorySize, smem64);

    const int gN  = (N + 255) / 256;
    const int gE  = (E + 255) / 256;
    const int gG  = (N + 127) / 128;
    const int gGa = (N * 16 + 255) / 256;
    const int gO  = (N * 64 + 255) / 256;
    const int nb  = (N + 1023) / 1024;
    const double inv_n = 1.0 / (double)N;

    // CSR build (once, reused by all 3 layers)
    deg_init_kernel  <<<gN, 256>>>(N);
    deg_count_kernel <<<gE, 256>>>(dst, E);
    scan_bsum_kernel <<<nb, 256>>>(N);
    scan_tops_kernel <<<1, 32>>>(nb, N, E);
    scan_final_kernel<<<nb, 1024>>>(N);
    fill_adj_kernel  <<<gE, 256>>>(src, dst, E);

    // ---- Layer 1 ----
    gemm_mma_kernel<128, false><<<gG, 256, smem128>>>(x, W1, nullptr, N);
    gather_kernel   <<<gGa, 256>>>(N);
    stats_kernel    <<<gN, 256>>>(N);
    finalize_kernel <<<1, 64>>>(G1, BE1, inv_n);

    // ---- Layer 2 ----
    gemm_mma_kernel<64, true><<<gG, 256, smem64>>>(nullptr, W2, A1, N);
    gather_kernel   <<<gGa, 256>>>(N);
    stats_kernel    <<<gN, 256>>>(N);
    finalize_kernel <<<1, 64>>>(G2, BE2, inv_n);

    // ---- Layer 3 ----
    gemm_mma_kernel<64, true><<<gG, 256, smem64>>>(nullptr, W3, A2, N);
    gather_kernel   <<<gGa, 256>>>(N);
    stats_kernel    <<<gN, 256>>>(N);
    finalize_kernel <<<1, 64>>>(G3, BE3, inv_n);

    out_kernel<<<gO, 256>>>(A3, (float*)d_out, N);
}